// round 12
// baseline (speedup 1.0000x reference)
#include <cuda_runtime.h>
#include <cuda_fp16.h>
#include <math.h>
#include <stdint.h>

// Problem constants
#define BB   2
#define LL   1024
#define DD   768
#define HH   12
#define HD   64
#define NLAY 2
#define DFFN 3072
#define VV   50257
#define EOS_ID 50256
#define ROWS (BB*LL)          // 2048

// ---------------------------------------------------------------------------
// Static scratch
// ---------------------------------------------------------------------------
__device__ float  g_x[ROWS*DD];
__device__ float  g_tmp[ROWS*DD];
__device__ int    g_rel[ROWS];
__device__ int    g_seg[ROWS];
// fp16 activations
__device__ __half h_qkv[ROWS*3*DD];
__device__ __half h_x[ROWS*DD];
__device__ __half h_att[ROWS*DD];
__device__ __half h_ff[ROWS*DFFN];

__device__ __forceinline__ uint32_t smem_u32(const void* p) {
    uint32_t a;
    asm("{ .reg .u64 t; cvta.to.shared.u64 t, %1; cvt.u32.u64 %0, t; }"
        : "=r"(a) : "l"(p));
    return a;
}

__device__ __forceinline__ uint32_t packh2(float x, float y) {
    __half2 h = __floats2half2_rn(x, y);
    return *reinterpret_cast<uint32_t*>(&h);
}

__device__ __forceinline__ void ldsm_x4(uint32_t addr, uint32_t& r0, uint32_t& r1,
                                        uint32_t& r2, uint32_t& r3) {
    asm volatile("ldmatrix.sync.aligned.m8n8.x4.shared.b16 {%0,%1,%2,%3}, [%4];"
                 : "=r"(r0), "=r"(r1), "=r"(r2), "=r"(r3) : "r"(addr));
}

__device__ __forceinline__ void ldsm_x4_t(uint32_t addr, uint32_t& r0, uint32_t& r1,
                                          uint32_t& r2, uint32_t& r3) {
    asm volatile("ldmatrix.sync.aligned.m8n8.x4.trans.shared.b16 {%0,%1,%2,%3}, [%4];"
                 : "=r"(r0), "=r"(r1), "=r"(r2), "=r"(r3) : "r"(addr));
}

#define MMA16816(d, a0,a1,a2,a3, b0,b1) \
    asm volatile( \
        "mma.sync.aligned.m16n8k16.row.col.f32.f16.f16.f32 " \
        "{%0,%1,%2,%3}, {%4,%5,%6,%7}, {%8,%9}, {%0,%1,%2,%3};\n" \
        : "+f"((d)[0]), "+f"((d)[1]), "+f"((d)[2]), "+f"((d)[3]) \
        : "r"(a0), "r"(a1), "r"(a2), "r"(a3), "r"(b0), "r"(b1))

// ---------------------------------------------------------------------------
// Meta + embedding
// ---------------------------------------------------------------------------
__global__ void meta_kernel(const int* __restrict__ ids, int* __restrict__ rel,
                            int* __restrict__ seg) {
    int b = blockIdx.x;
    if (threadIdx.x != 0) return;
    int last = 0, s = 0;
    for (int l = 0; l < LL; l++) {
        int id = ids[b*LL + l];
        if (id == EOS_ID) { last = l; s += 1; }
        rel[b*LL + l] = l - last;
        seg[b*LL + l] = s;
    }
}

__global__ void embed_kernel(const int* __restrict__ ids, const int* __restrict__ rel,
                             const float* __restrict__ tok, const float* __restrict__ pos,
                             float* __restrict__ x, __half* __restrict__ hx) {
    int row = blockIdx.x;
    int id = ids[row];
    int r  = rel[row];
    const float* t = tok + (size_t)id * DD;
    const float* p = pos + (size_t)r  * DD;
    const float sc = 27.712812921102035f;  // sqrt(768)
    for (int i = threadIdx.x; i < DD; i += blockDim.x) {
        float v = t[i] * sc + p[i];
        x[(size_t)row*DD + i]  = v;
        hx[(size_t)row*DD + i] = __float2half(v);
    }
}

#define HSTR 40   // halves per smem row for GEMM (32 data + 8 pad)

// ---------------------------------------------------------------------------
// Mixed-operand GEMM: C[M,N] = A_fp16[M,K] @ B_fp32[N,K]^T (+bias)(+GELU)
// 128x128 tile, BK=32, 8 warps, 32x64 warp tile, ldmatrix + m16n8k16.
// B converted fp32->fp16 at smem store (weights read once -> no pre-conv).
// OUTH -> fp16 C (N even). Grid: x = M-tile fast. M%128==0, K%32==0.
// ---------------------------------------------------------------------------
template<bool GELU, bool OUTH>
__global__ __launch_bounds__(256, 2)
void gemm_h(const __half* __restrict__ A, const float* __restrict__ B,
            const float* __restrict__ bias, void* __restrict__ Cv,
            int M, int N, int K) {
    __shared__ __align__(16) __half SA[2][128*HSTR];
    __shared__ __align__(16) __half SB[2][128*HSTR];

    const int bm = blockIdx.x * 128;
    const int bn = blockIdx.y * 128;
    const int tid  = threadIdx.x;
    const int warp = tid >> 5;
    const int lane = tid & 31;
    const int grp  = lane >> 2;
    const int qid  = lane & 3;

    const int wm = (warp >> 1) * 32;
    const int wn = (warp & 1) * 64;

    const int lrow  = lane & 15;
    const int lcol8 = (lane >> 4) << 3;
    uint32_t aoff[2], boff[4];
#pragma unroll
    for (int i = 0; i < 2; i++)
        aoff[i] = ((wm + i*16 + lrow) * HSTR + lcol8) * 2;
#pragma unroll
    for (int p = 0; p < 4; p++)
        boff[p] = ((wn + p*16 + lrow) * HSTR + lcol8) * 2;

    const uint32_t sa0 = smem_u32(&SA[0][0]), sa1 = smem_u32(&SA[1][0]);
    const uint32_t sb0 = smem_u32(&SB[0][0]), sb1 = smem_u32(&SB[1][0]);

    float acc[2][8][4];
#pragma unroll
    for (int i = 0; i < 2; i++)
#pragma unroll
        for (int j = 0; j < 8; j++)
#pragma unroll
            for (int c = 0; c < 4; c++) acc[i][j][c] = 0.f;

    const int ntiles = K >> 5;
    uint4  rA[2];
    float4 rB[4];
    const uint4  zeroA = make_uint4(0u, 0u, 0u, 0u);
    const float4 zeroB = make_float4(0.f, 0.f, 0.f, 0.f);

    // A loader: 2x uint4 (8 halves) per thread; B loader: 4x float4 per thread
#pragma unroll
    for (int i = 0; i < 2; i++) {
        int idx = tid + (i << 8);
        int row = idx >> 2;
        int s8  = (idx & 3) << 3;
        rA[i] = *reinterpret_cast<const uint4*>(A + (size_t)(bm + row) * K + s8);
    }
#pragma unroll
    for (int i = 0; i < 4; i++) {
        int idx = tid + (i << 8);
        int row = idx >> 3;
        int f4  = (idx & 7) << 2;
        int gn  = bn + row;
        rB[i] = (gn < N) ? *reinterpret_cast<const float4*>(B + (size_t)gn * K + f4)
                         : zeroB;
    }
#pragma unroll
    for (int i = 0; i < 2; i++) {
        int idx = tid + (i << 8);
        int row = idx >> 2;
        int s8  = (idx & 3) << 3;
        *reinterpret_cast<uint4*>(&SA[0][row*HSTR + s8]) = rA[i];
    }
#pragma unroll
    for (int i = 0; i < 4; i++) {
        int idx = tid + (i << 8);
        int row = idx >> 3;
        int f4  = (idx & 7) << 2;
        *reinterpret_cast<uint2*>(&SB[0][row*HSTR + f4]) =
            make_uint2(packh2(rB[i].x, rB[i].y), packh2(rB[i].z, rB[i].w));
    }
    __syncthreads();

    for (int t = 0; t < ntiles; t++) {
        const int cb = t & 1;
        const bool more = (t + 1 < ntiles);

        if (more) {
            int kt = (t + 1) << 5;
#pragma unroll
            for (int i = 0; i < 2; i++) {
                int idx = tid + (i << 8);
                int row = idx >> 2;
                int s8  = (idx & 3) << 3;
                rA[i] = *reinterpret_cast<const uint4*>(A + (size_t)(bm + row) * K + kt + s8);
            }
#pragma unroll
            for (int i = 0; i < 4; i++) {
                int idx = tid + (i << 8);
                int row = idx >> 3;
                int f4  = (idx & 7) << 2;
                int gn  = bn + row;
                rB[i] = (gn < N) ? *reinterpret_cast<const float4*>(B + (size_t)gn * K + kt + f4)
                                 : zeroB;
            }
        }

        const uint32_t sa = cb ? sa1 : sa0;
        const uint32_t sb = cb ? sb1 : sb0;
#pragma unroll
        for (int ks = 0; ks < 2; ks++) {
            const uint32_t kb = ks * 32;
            uint32_t af[2][4];
#pragma unroll
            for (int i = 0; i < 2; i++)
                ldsm_x4(sa + aoff[i] + kb, af[i][0], af[i][1], af[i][2], af[i][3]);
#pragma unroll
            for (int p = 0; p < 4; p++) {
                uint32_t bf[4];
                ldsm_x4(sb + boff[p] + kb, bf[0], bf[1], bf[2], bf[3]);
#pragma unroll
                for (int i = 0; i < 2; i++) {
                    MMA16816(acc[i][2*p],   af[i][0], af[i][1], af[i][2], af[i][3], bf[0], bf[2]);
                    MMA16816(acc[i][2*p+1], af[i][0], af[i][1], af[i][2], af[i][3], bf[1], bf[3]);
                }
            }
        }

        if (more) {
            const int nb = (t + 1) & 1;
#pragma unroll
            for (int i = 0; i < 2; i++) {
                int idx = tid + (i << 8);
                int row = idx >> 2;
                int s8  = (idx & 3) << 3;
                *reinterpret_cast<uint4*>(&SA[nb][row*HSTR + s8]) = rA[i];
            }
#pragma unroll
            for (int i = 0; i < 4; i++) {
                int idx = tid + (i << 8);
                int row = idx >> 3;
                int f4  = (idx & 7) << 2;
                *reinterpret_cast<uint2*>(&SB[nb][row*HSTR + f4]) =
                    make_uint2(packh2(rB[i].x, rB[i].y), packh2(rB[i].z, rB[i].w));
            }
        }
        __syncthreads();
    }

    float*  Cf = reinterpret_cast<float*>(Cv);
    __half* Ch = reinterpret_cast<__half*>(Cv);
    const bool evenN = (N & 1) == 0;
#pragma unroll
    for (int i = 0; i < 2; i++) {
#pragma unroll
        for (int j = 0; j < 8; j++) {
#pragma unroll
            for (int pr = 0; pr < 2; pr++) {
                int row = bm + wm + i*16 + grp + pr*8;
                int col = bn + wn + j*8 + (qid << 1);
                float v0 = acc[i][j][2*pr + 0];
                float v1 = acc[i][j][2*pr + 1];
                if (bias) { v0 += bias[col]; if (col + 1 < N) v1 += bias[col + 1]; }
                if (GELU) {
                    v0 = 0.5f * v0 * (1.0f + erff(v0 * 0.7071067811865475f));
                    v1 = 0.5f * v1 * (1.0f + erff(v1 * 0.7071067811865475f));
                }
                size_t base = (size_t)row * N + col;
                if (OUTH) {
                    if (col + 1 < N) {
                        *reinterpret_cast<uint32_t*>(&Ch[base]) = packh2(v0, v1);
                    } else if (col < N) {
                        Ch[base] = __float2half(v0);
                    }
                } else {
                    if (col + 1 < N) {
                        if (evenN) *reinterpret_cast<float2*>(&Cf[base]) = make_float2(v0, v1);
                        else { Cf[base] = v0; Cf[base + 1] = v1; }
                    } else if (col < N) {
                        Cf[base] = v0;
                    }
                }
            }
        }
    }
}

// ---------------------------------------------------------------------------
// Tensor-core flash attention, fp16 qkv input (q-tile 128, kv-tile 64).
// ---------------------------------------------------------------------------
#define ASTR 72   // halves per attention smem row (64 data + 8 pad)

__global__ __launch_bounds__(256, 2)
void attn_mma_kernel(const __half* __restrict__ qkv, const int* __restrict__ seg,
                     __half* __restrict__ o) {
    __shared__ __align__(16) __half Qh[128*ASTR];
    __shared__ __align__(16) __half Kh[64*ASTR];
    __shared__ __align__(16) __half Vh[64*ASTR];
    __shared__ int sseg[64];

    const int qt = blockIdx.x;       // 0..7
    const int h  = blockIdx.y;
    const int b  = blockIdx.z;
    const int tid  = threadIdx.x;
    const int warp = tid >> 5;
    const int lane = tid & 31;
    const int grp  = lane >> 2;
    const int qid  = lane & 3;
    const int q0 = qt * 128;

    const uint32_t qbase = smem_u32(Qh);
    const uint32_t kbase = smem_u32(Kh);
    const uint32_t vbase = smem_u32(Vh);
    const int lrow  = lane & 15;
    const int lcol8 = (lane >> 4) << 3;

    // load Q (scaled by exact 0.125 in fp16) -> smem
    const __half2 sc2 = __floats2half2_rn(0.125f, 0.125f);
#pragma unroll
    for (int i = 0; i < 4; i++) {
        int idx = tid + (i << 8);
        int r  = idx >> 3;
        int c8 = (idx & 7) << 3;
        uint4 v = *reinterpret_cast<const uint4*>(
            qkv + (size_t)(b*LL + q0 + r)*(3*DD) + h*HD + c8);
        __half2* hv = reinterpret_cast<__half2*>(&v);
#pragma unroll
        for (int c = 0; c < 4; c++) hv[c] = __hmul2(hv[c], sc2);
        *reinterpret_cast<uint4*>(&Qh[r*ASTR + c8]) = v;
    }

    const int qg0 = q0 + warp*16 + grp;
    const int qg1 = qg0 + 8;
    const int qseg0 = seg[b*LL + qg0];
    const int qseg1 = seg[b*LL + qg1];

    float m0 = -1e30f, m1 = -1e30f, l0 = 0.f, l1 = 0.f;
    float O[8][4];
#pragma unroll
    for (int j = 0; j < 8; j++)
#pragma unroll
        for (int c = 0; c < 4; c++) O[j][c] = 0.f;

    const int ntiles = 2*qt + 2;
    for (int kt = 0; kt < ntiles; kt++) {
        const int k0 = kt * 64;
        __syncthreads();
#pragma unroll
        for (int i = 0; i < 2; i++) {
            int idx = tid + (i << 8);
            int r  = idx >> 3;
            int c8 = (idx & 7) << 3;
            const __half* base = qkv + (size_t)(b*LL + k0 + r)*(3*DD) + h*HD + c8;
            *reinterpret_cast<uint4*>(&Kh[r*ASTR + c8]) =
                *reinterpret_cast<const uint4*>(base + DD);
            *reinterpret_cast<uint4*>(&Vh[r*ASTR + c8]) =
                *reinterpret_cast<const uint4*>(base + 2*DD);
        }
        if (tid < 64) sseg[tid] = seg[b*LL + k0 + tid];
        __syncthreads();

        float s[8][4];
#pragma unroll
        for (int j = 0; j < 8; j++)
#pragma unroll
            for (int c = 0; c < 4; c++) s[j][c] = 0.f;
#pragma unroll
        for (int ks = 0; ks < 4; ks++) {
            uint32_t aq[4];
            ldsm_x4(qbase + ((warp*16 + lrow)*ASTR + ks*16 + lcol8)*2,
                    aq[0], aq[1], aq[2], aq[3]);
#pragma unroll
            for (int p = 0; p < 4; p++) {
                uint32_t bf[4];
                ldsm_x4(kbase + ((p*16 + lrow)*ASTR + ks*16 + lcol8)*2,
                        bf[0], bf[1], bf[2], bf[3]);
                MMA16816(s[2*p],   aq[0], aq[1], aq[2], aq[3], bf[0], bf[2]);
                MMA16816(s[2*p+1], aq[0], aq[1], aq[2], aq[3], bf[1], bf[3]);
            }
        }

        float mt0 = -1e30f, mt1 = -1e30f;
#pragma unroll
        for (int j = 0; j < 8; j++) {
            int kg0 = k0 + 8*j + 2*qid;
            int sg0 = sseg[8*j + 2*qid];
            int sg1 = sseg[8*j + 2*qid + 1];
            s[j][0] = (kg0     <= qg0 && sg0 == qseg0) ? s[j][0] : -1e30f;
            s[j][1] = (kg0 + 1 <= qg0 && sg1 == qseg0) ? s[j][1] : -1e30f;
            s[j][2] = (kg0     <= qg1 && sg0 == qseg1) ? s[j][2] : -1e30f;
            s[j][3] = (kg0 + 1 <= qg1 && sg1 == qseg1) ? s[j][3] : -1e30f;
            mt0 = fmaxf(mt0, fmaxf(s[j][0], s[j][1]));
            mt1 = fmaxf(mt1, fmaxf(s[j][2], s[j][3]));
        }
#pragma unroll
        for (int off = 1; off < 4; off <<= 1) {
            mt0 = fmaxf(mt0, __shfl_xor_sync(0xffffffffu, mt0, off));
            mt1 = fmaxf(mt1, __shfl_xor_sync(0xffffffffu, mt1, off));
        }
        float mn0 = fmaxf(m0, mt0), mn1 = fmaxf(m1, mt1);
        float f0 = __expf(m0 - mn0), f1 = __expf(m1 - mn1);
        m0 = mn0; m1 = mn1;
        float rs0 = 0.f, rs1 = 0.f;
#pragma unroll
        for (int j = 0; j < 8; j++) {
            s[j][0] = __expf(s[j][0] - mn0);
            s[j][1] = __expf(s[j][1] - mn0);
            s[j][2] = __expf(s[j][2] - mn1);
            s[j][3] = __expf(s[j][3] - mn1);
            rs0 += s[j][0] + s[j][1];
            rs1 += s[j][2] + s[j][3];
            O[j][0] *= f0; O[j][1] *= f0;
            O[j][2] *= f1; O[j][3] *= f1;
        }
#pragma unroll
        for (int off = 1; off < 4; off <<= 1) {
            rs0 += __shfl_xor_sync(0xffffffffu, rs0, off);
            rs1 += __shfl_xor_sync(0xffffffffu, rs1, off);
        }
        l0 = l0 * f0 + rs0;
        l1 = l1 * f1 + rs1;

        uint32_t ap[4][4];
#pragma unroll
        for (int ks = 0; ks < 4; ks++) {
            ap[ks][0] = packh2(s[2*ks][0],   s[2*ks][1]);
            ap[ks][1] = packh2(s[2*ks][2],   s[2*ks][3]);
            ap[ks][2] = packh2(s[2*ks+1][0], s[2*ks+1][1]);
            ap[ks][3] = packh2(s[2*ks+1][2], s[2*ks+1][3]);
        }

#pragma unroll
        for (int ks = 0; ks < 4; ks++) {
#pragma unroll
            for (int p = 0; p < 4; p++) {
                uint32_t bv[4];
                ldsm_x4_t(vbase + ((ks*16 + lrow)*ASTR + p*16 + lcol8)*2,
                          bv[0], bv[1], bv[2], bv[3]);
                MMA16816(O[2*p],   ap[ks][0], ap[ks][1], ap[ks][2], ap[ks][3], bv[0], bv[1]);
                MMA16816(O[2*p+1], ap[ks][0], ap[ks][1], ap[ks][2], ap[ks][3], bv[2], bv[3]);
            }
        }
    }

    float inv0 = 1.0f / l0, inv1 = 1.0f / l1;
#pragma unroll
    for (int j = 0; j < 8; j++) {
        int col = h*HD + 8*j + 2*qid;
        *reinterpret_cast<uint32_t*>(&o[(size_t)(b*LL + qg0)*DD + col]) =
            packh2(O[j][0]*inv0, O[j][1]*inv0);
        *reinterpret_cast<uint32_t*>(&o[(size_t)(b*LL + qg1)*DD + col]) =
            packh2(O[j][2]*inv1, O[j][3]*inv1);
    }
}

// ---------------------------------------------------------------------------
// Block reduction + fused add+LN
// ---------------------------------------------------------------------------
__device__ __forceinline__ float block_sum256(float v, volatile float* red) {
#pragma unroll
    for (int o = 16; o; o >>= 1) v += __shfl_xor_sync(0xffffffffu, v, o);
    if ((threadIdx.x & 31) == 0) red[threadIdx.x >> 5] = v;
    __syncthreads();
    if (threadIdx.x == 0) {
        float s = red[0];
#pragma unroll
        for (int i = 1; i < 8; i++) s += red[i];
        red[0] = s;
    }
    __syncthreads();
    float r = red[0];
    __syncthreads();
    return r;
}

__global__ __launch_bounds__(256)
void add_ln_kernel(float* __restrict__ x, const float* __restrict__ r,
                   const float* __restrict__ w, const float* __restrict__ b,
                   __half* __restrict__ hx) {
    int row = blockIdx.x;
    int tid = threadIdx.x;
    __shared__ float buf[DD];
    __shared__ float red[8];

    float s = 0.f;
    for (int i = tid; i < DD; i += 256) {
        float v = x[(size_t)row*DD + i] + r[(size_t)row*DD + i];
        buf[i] = v;
        s += v;
    }
    __syncthreads();
    float mean = block_sum256(s, red) * (1.0f / DD);

    float vs = 0.f;
    for (int i = tid; i < DD; i += 256) {
        float d = buf[i] - mean;
        vs += d * d;
    }
    float var = block_sum256(vs, red) * (1.0f / DD);
    float inv = rsqrtf(var + 1e-5f);

    for (int i = tid; i < DD; i += 256) {
        float v = (buf[i] - mean) * inv * w[i] + b[i];
        x[(size_t)row*DD + i]  = v;
        hx[(size_t)row*DD + i] = __float2half(v);
    }
}

// ---------------------------------------------------------------------------
// Host launcher
// ---------------------------------------------------------------------------
extern "C" void kernel_launch(void* const* d_in, const int* in_sizes, int n_in,
                              void* d_out, int out_size) {
    const int*   ids   = (const int*)  d_in[0];
    const float* tok   = (const float*)d_in[1];
    const float* pos   = (const float*)d_in[2];
    const float* qkv_w = (const float*)d_in[3];
    const float* qkv_b = (const float*)d_in[4];
    const float* out_w = (const float*)d_in[5];
    const float* out_b = (const float*)d_in[6];
    const float* ln1_w = (const float*)d_in[7];
    const float* ln1_b = (const float*)d_in[8];
    const float* ln2_w = (const float*)d_in[9];
    const float* ln2_b = (const float*)d_in[10];
    const float* ff1_w = (const float*)d_in[11];
    const float* ff1_b = (const float*)d_in[12];
    const float* ff2_w = (const float*)d_in[13];
    const float* ff2_b = (const float*)d_in[14];
    float* out = (float*)d_out;

    float *x, *tmp;
    int *rel, *seg;
    __half *hqkv, *hx, *hatt, *hff;
    cudaGetSymbolAddress((void**)&x,    g_x);
    cudaGetSymbolAddress((void**)&tmp,  g_tmp);
    cudaGetSymbolAddress((void**)&rel,  g_rel);
    cudaGetSymbolAddress((void**)&seg,  g_seg);
    cudaGetSymbolAddress((void**)&hqkv, h_qkv);
    cudaGetSymbolAddress((void**)&hx,   h_x);
    cudaGetSymbolAddress((void**)&hatt, h_att);
    cudaGetSymbolAddress((void**)&hff,  h_ff);

    meta_kernel<<<BB, 32>>>(ids, rel, seg);
    embed_kernel<<<ROWS, 256>>>(ids, rel, tok, pos, x, hx);

    const int MT = ROWS / 128;  // 16, fast axis

    for (int l = 0; l < NLAY; l++) {
        gemm_h<false,true><<<dim3(MT, 3*DD/128), 256>>>(
            hx, qkv_w + (size_t)l*3*DD*DD, qkv_b + (size_t)l*3*DD, hqkv,
            ROWS, 3*DD, DD);

        attn_mma_kernel<<<dim3(LL/128, HH, BB), 256>>>(hqkv, seg, hatt);

        gemm_h<false,false><<<dim3(MT, DD/128), 256>>>(
            hatt, out_w + (size_t)l*DD*DD, out_b + (size_t)l*DD, tmp,
            ROWS, DD, DD);

        add_ln_kernel<<<ROWS, 256>>>(x, tmp, ln1_w + (size_t)l*DD, ln1_b + (size_t)l*DD, hx);

        gemm_h<true,true><<<dim3(MT, DFFN/128), 256>>>(
            hx, ff1_w + (size_t)l*DFFN*DD, ff1_b + (size_t)l*DFFN, hff,
            ROWS, DFFN, DD);

        gemm_h<false,false><<<dim3(MT, DD/128), 256>>>(
            hff, ff2_w + (size_t)l*DD*DFFN, ff2_b + (size_t)l*DD, tmp,
            ROWS, DD, DFFN);

        add_ln_kernel<<<ROWS, 256>>>(x, tmp, ln2_w + (size_t)l*DD, ln2_b + (size_t)l*DD, hx);
    }

    gemm_h<false,false><<<dim3(MT, (VV + 127)/128), 256>>>(
        hx, tok, nullptr, out, ROWS, VV, DD);
}